// round 2
// baseline (speedup 1.0000x reference)
#include <cuda_runtime.h>
#include <math.h>

#define D_MODEL 1024
#define N_HEADS 16
#define HEAD_DIM 64
#define D_FF 4096
#define ROPE_RANK 16
#define BB 2
#define TT 2048
#define MROWS (BB*TT)   // 4096

// ---------------- scratch (static device allocations; no cudaMalloc) ----------
__device__ float g_q[MROWS*D_MODEL];
__device__ float g_k[MROWS*D_MODEL];
__device__ float g_v[MROWS*D_MODEL];
__device__ float g_ctx[MROWS*D_MODEL];
__device__ float g_x[MROWS*D_MODEL];
__device__ float g_x1[MROWS*D_MODEL];
__device__ float g_ff[MROWS*D_FF];
__device__ float g_sinf[TT*512];
__device__ float g_cosf[TT*512];

// ---------------- RoPE factor precompute -------------------------------------
// sin_f[t][i] = sin(t*theta_i) + (base_t @ A @ B)[i]
// cos_f[t][i] = cos(t*theta_i) + (base_t @ A @ B)[512+i]
__global__ void rope_factors_kernel(const float* __restrict__ A,
                                    const float* __restrict__ Bm,
                                    float* __restrict__ sf, float* __restrict__ cf)
{
    int t = blockIdx.x;
    __shared__ float base[1024];
    __shared__ float tmp[ROPE_RANK];
    __shared__ float wred[8][ROPE_RANK];
    int tid = threadIdx.x;

    for (int j = tid; j < 1024; j += 256) {
        int i = j & 511;
        double theta_d = exp(-log(10000.0) * (double)i / 512.0);
        float theta = (float)theta_d;
        float ang = (float)t * theta;   // fp32 product, matching reference quantization
        base[j] = (j < 512) ? sinf(ang) : cosf(ang);
    }
    __syncthreads();

    float loc[ROPE_RANK];
#pragma unroll
    for (int r = 0; r < ROPE_RANK; r++) loc[r] = 0.f;
    for (int j = tid; j < 1024; j += 256) {
        float bj = base[j];
#pragma unroll
        for (int r = 0; r < ROPE_RANK; r++) loc[r] += bj * A[j*ROPE_RANK + r];
    }
#pragma unroll
    for (int r = 0; r < ROPE_RANK; r++) {
#pragma unroll
        for (int off = 16; off; off >>= 1)
            loc[r] += __shfl_xor_sync(0xffffffffu, loc[r], off);
    }
    int warp = tid >> 5, lane = tid & 31;
    if (lane == 0) {
#pragma unroll
        for (int r = 0; r < ROPE_RANK; r++) wred[warp][r] = loc[r];
    }
    __syncthreads();
    if (tid < ROPE_RANK) {
        float s = 0.f;
#pragma unroll
        for (int w = 0; w < 8; w++) s += wred[w][tid];
        tmp[tid] = s;
    }
    __syncthreads();

    for (int d = tid; d < 1024; d += 256) {
        float s = 0.f;
#pragma unroll
        for (int r = 0; r < ROPE_RANK; r++) s += tmp[r] * Bm[r*1024 + d];
        float val = base[d] + s;
        if (d < 512) sf[t*512 + d]       = val;
        else         cf[t*512 + d - 512] = val;
    }
}

// ---------------- RoPE apply (interleaved pairs) to q and k in place ---------
__global__ void rope_apply_kernel(float* __restrict__ q, float* __restrict__ k,
                                  const float* __restrict__ sf, const float* __restrict__ cf)
{
    int idx = blockIdx.x * blockDim.x + threadIdx.x;   // over MROWS*512
    if (idx >= MROWS*512) return;
    int p   = idx & 511;
    int row = idx >> 9;
    int t   = row & (TT-1);
    float s = sf[t*512 + p];
    float c = cf[t*512 + p];
    size_t base = (size_t)row*D_MODEL + 2*p;
    float qe = q[base], qo = q[base+1];
    q[base]   = qe*c - qo*s;
    q[base+1] = qe*s + qo*c;
    float ke = k[base], ko = k[base+1];
    k[base]   = ke*c - ko*s;
    k[base+1] = ke*s + ko*c;
}

// ---------------- SGEMM: C[M,N] = A[M,K] @ W[K,N] + bias (+resid) (+relu) ----
// 128x128 tile, BK=8, 256 threads, 8x8 micro-tile.
__global__ __launch_bounds__(256)
void sgemm_kernel(const float* __restrict__ A, const float* __restrict__ Bm,
                  const float* __restrict__ bias, const float* __restrict__ resid,
                  float* __restrict__ C, int M, int N, int K, int relu)
{
    __shared__ float As[8][128];
    __shared__ float Bs[8][128];
    int tid = threadIdx.x;
    int m0 = blockIdx.y * 128, n0 = blockIdx.x * 128;
    int tx = tid & 15, ty = tid >> 4;
    int r0 = ty * 8, c0 = tx * 8;

    float acc[8][8];
#pragma unroll
    for (int i = 0; i < 8; i++)
#pragma unroll
        for (int j = 0; j < 8; j++) acc[i][j] = 0.f;

    int arow = tid >> 1, acol = (tid & 1) * 4;
    int brow = tid >> 5, bcol = (tid & 31) * 4;
    const float* Aptr = A + (size_t)(m0 + arow) * K + acol;
    const float* Bptr = Bm + (size_t)brow * N + n0 + bcol;

    for (int kt = 0; kt < K; kt += 8) {
        float4 av = *(const float4*)Aptr;
        float4 bv = *(const float4*)Bptr;
        As[acol+0][arow] = av.x;
        As[acol+1][arow] = av.y;
        As[acol+2][arow] = av.z;
        As[acol+3][arow] = av.w;
        *(float4*)&Bs[brow][bcol] = bv;
        __syncthreads();
#pragma unroll
        for (int k = 0; k < 8; k++) {
            float4 a0 = *(float4*)&As[k][r0];
            float4 a1 = *(float4*)&As[k][r0+4];
            float4 b0 = *(float4*)&Bs[k][c0];
            float4 b1 = *(float4*)&Bs[k][c0+4];
            float a[8] = {a0.x,a0.y,a0.z,a0.w,a1.x,a1.y,a1.z,a1.w};
            float b[8] = {b0.x,b0.y,b0.z,b0.w,b1.x,b1.y,b1.z,b1.w};
#pragma unroll
            for (int i = 0; i < 8; i++)
#pragma unroll
                for (int j = 0; j < 8; j++)
                    acc[i][j] += a[i] * b[j];
        }
        __syncthreads();
        Aptr += 8;
        Bptr += (size_t)8 * N;
    }

#pragma unroll
    for (int i = 0; i < 8; i++) {
        size_t row = (size_t)(m0 + r0 + i);
#pragma unroll
        for (int j = 0; j < 8; j++) {
            int col = n0 + c0 + j;
            float v = acc[i][j];
            if (bias)  v += bias[col];
            if (resid) v += resid[row * N + col];
            if (relu)  v = fmaxf(v, 0.f);
            C[row * N + col] = v;
        }
    }
}

// ---------------- Flash attention (fp32, no mask) ----------------------------
// grid: (T/64, B*H); block 256. smem: Qs/Ks/Vt/Ps each 64x68 floats.
#define AP 68
__global__ __launch_bounds__(256)
void attention_kernel(const float* __restrict__ q, const float* __restrict__ k,
                      const float* __restrict__ v, float* __restrict__ ctx)
{
    extern __shared__ float sm[];
    float* Qs = sm;
    float* Ks = Qs + 64*AP;
    float* Vt = Ks + 64*AP;
    float* Ps = Vt + 64*AP;

    int qblk = blockIdx.x;
    int bh   = blockIdx.y;
    int b = bh >> 4, h = bh & 15;
    int tid = threadIdx.x;
    int tx = tid & 15, ty = tid >> 4;
    const float scale = 0.125f;   // 1/sqrt(64)

    int q0 = qblk * 64;
    size_t rowbase = (size_t)b * TT;
    int colbase = h * HEAD_DIM;

    // load Q tile (pre-scaled)
    for (int i = tid; i < 64*16; i += 256) {
        int r = i >> 4, c4 = (i & 15) * 4;
        float4 val = *(const float4*)&q[(rowbase + q0 + r)*D_MODEL + colbase + c4];
        val.x *= scale; val.y *= scale; val.z *= scale; val.w *= scale;
        *(float4*)&Qs[r*AP + c4] = val;
    }
    __syncthreads();

    float m_i[4], l_i[4], acc[4][4];
#pragma unroll
    for (int i = 0; i < 4; i++) {
        m_i[i] = -1e30f; l_i[i] = 0.f;
#pragma unroll
        for (int j = 0; j < 4; j++) acc[i][j] = 0.f;
    }

    for (int kt = 0; kt < TT; kt += 64) {
        // load K tile, V transposed
        for (int i = tid; i < 64*16; i += 256) {
            int r = i >> 4, c4 = (i & 15) * 4;
            *(float4*)&Ks[r*AP + c4] =
                *(const float4*)&k[(rowbase + kt + r)*D_MODEL + colbase + c4];
            float4 vv = *(const float4*)&v[(rowbase + kt + r)*D_MODEL + colbase + c4];
            Vt[(c4+0)*AP + r] = vv.x;
            Vt[(c4+1)*AP + r] = vv.y;
            Vt[(c4+2)*AP + r] = vv.z;
            Vt[(c4+3)*AP + r] = vv.w;
        }
        __syncthreads();

        // S = Q K^T  (4x4 per thread)
        float s[4][4];
#pragma unroll
        for (int i = 0; i < 4; i++)
#pragma unroll
            for (int j = 0; j < 4; j++) s[i][j] = 0.f;
#pragma unroll
        for (int d4 = 0; d4 < 16; d4++) {
            float4 a[4], bb[4];
#pragma unroll
            for (int i = 0; i < 4; i++) a[i]  = *(float4*)&Qs[(4*ty+i)*AP + d4*4];
#pragma unroll
            for (int j = 0; j < 4; j++) bb[j] = *(float4*)&Ks[(4*tx+j)*AP + d4*4];
#pragma unroll
            for (int i = 0; i < 4; i++)
#pragma unroll
                for (int j = 0; j < 4; j++)
                    s[i][j] += a[i].x*bb[j].x + a[i].y*bb[j].y + a[i].z*bb[j].z + a[i].w*bb[j].w;
        }

        // online softmax per query row (rows shared across the 16-lane tx group)
#pragma unroll
        for (int i = 0; i < 4; i++) {
            float tm = fmaxf(fmaxf(s[i][0], s[i][1]), fmaxf(s[i][2], s[i][3]));
#pragma unroll
            for (int off = 1; off < 16; off <<= 1)
                tm = fmaxf(tm, __shfl_xor_sync(0xffffffffu, tm, off));
            float m_new = fmaxf(m_i[i], tm);
            float corr  = __expf(m_i[i] - m_new);
            float rs = 0.f;
#pragma unroll
            for (int j = 0; j < 4; j++) {
                float p = __expf(s[i][j] - m_new);
                s[i][j] = p;
                rs += p;
            }
#pragma unroll
            for (int off = 1; off < 16; off <<= 1)
                rs += __shfl_xor_sync(0xffffffffu, rs, off);
            l_i[i] = l_i[i]*corr + rs;
            m_i[i] = m_new;
#pragma unroll
            for (int j = 0; j < 4; j++) {
                acc[i][j] *= corr;
                Ps[(4*ty+i)*AP + 4*tx+j] = s[i][j];
            }
        }
        __syncthreads();

        // acc += P @ V  (via V transposed: both operands contiguous in kk)
#pragma unroll
        for (int k4 = 0; k4 < 16; k4++) {
            float4 p[4], vv[4];
#pragma unroll
            for (int i = 0; i < 4; i++) p[i]  = *(float4*)&Ps[(4*ty+i)*AP + k4*4];
#pragma unroll
            for (int j = 0; j < 4; j++) vv[j] = *(float4*)&Vt[(4*tx+j)*AP + k4*4];
#pragma unroll
            for (int i = 0; i < 4; i++)
#pragma unroll
                for (int j = 0; j < 4; j++)
                    acc[i][j] += p[i].x*vv[j].x + p[i].y*vv[j].y + p[i].z*vv[j].z + p[i].w*vv[j].w;
        }
        __syncthreads();
    }

#pragma unroll
    for (int i = 0; i < 4; i++) {
        float inv = 1.f / l_i[i];
#pragma unroll
        for (int j = 0; j < 4; j++)
            ctx[(rowbase + q0 + 4*ty + i)*D_MODEL + colbase + 4*tx + j] = acc[i][j] * inv;
    }
}

// ---------------- LayerNorm over D=1024, one block per row -------------------
__global__ __launch_bounds__(256)
void layernorm_kernel(const float* __restrict__ x, const float* __restrict__ g,
                      const float* __restrict__ bvec, float* __restrict__ out)
{
    int row = blockIdx.x;
    int tid = threadIdx.x;
    const float* xr = x + (size_t)row * D_MODEL;
    float4 v = *(const float4*)&xr[tid*4];
    float s  = v.x + v.y + v.z + v.w;
    float s2 = v.x*v.x + v.y*v.y + v.z*v.z + v.w*v.w;
#pragma unroll
    for (int off = 16; off; off >>= 1) {
        s  += __shfl_xor_sync(0xffffffffu, s,  off);
        s2 += __shfl_xor_sync(0xffffffffu, s2, off);
    }
    __shared__ float ws[8], ws2[8];
    __shared__ float smu, sinv;
    int warp = tid >> 5;
    if ((tid & 31) == 0) { ws[warp] = s; ws2[warp] = s2; }
    __syncthreads();
    if (tid == 0) {
        float a = 0.f, b2 = 0.f;
#pragma unroll
        for (int w = 0; w < 8; w++) { a += ws[w]; b2 += ws2[w]; }
        float mu  = a * (1.f/1024.f);
        float var = b2 * (1.f/1024.f) - mu*mu;
        smu = mu;
        sinv = rsqrtf(var + 1e-5f);
    }
    __syncthreads();
    float mu = smu, inv = sinv;
    float4 gg  = *(const float4*)&g[tid*4];
    float4 bb4 = *(const float4*)&bvec[tid*4];
    float4 o;
    o.x = (v.x - mu)*inv*gg.x + bb4.x;
    o.y = (v.y - mu)*inv*gg.y + bb4.y;
    o.z = (v.z - mu)*inv*gg.z + bb4.z;
    o.w = (v.w - mu)*inv*gg.w + bb4.w;
    *(float4*)&out[(size_t)row * D_MODEL + tid*4] = o;
}

// ---------------- launch ------------------------------------------------------
extern "C" void kernel_launch(void* const* d_in, const int* in_sizes, int n_in,
                              void* d_out, int out_size)
{
    const float* tgt  = (const float*)d_in[0];
    const float* Wq   = (const float*)d_in[1];
    const float* bq   = (const float*)d_in[2];
    const float* Wk   = (const float*)d_in[3];
    const float* bk   = (const float*)d_in[4];
    const float* Wv   = (const float*)d_in[5];
    const float* bv   = (const float*)d_in[6];
    const float* Wo   = (const float*)d_in[7];
    const float* bo   = (const float*)d_in[8];
    const float* W1   = (const float*)d_in[9];
    const float* b1   = (const float*)d_in[10];
    const float* W2   = (const float*)d_in[11];
    const float* b2   = (const float*)d_in[12];
    const float* ln1g = (const float*)d_in[13];
    const float* ln1b = (const float*)d_in[14];
    const float* ln2g = (const float*)d_in[15];
    const float* ln2b = (const float*)d_in[16];
    const float* ropeA = (const float*)d_in[17];
    const float* ropeB = (const float*)d_in[18];
    float* out = (float*)d_out;

    float *pq, *pk, *pv, *pctx, *px, *px1, *pff, *psin, *pcos;
    cudaGetSymbolAddress((void**)&pq,   g_q);
    cudaGetSymbolAddress((void**)&pk,   g_k);
    cudaGetSymbolAddress((void**)&pv,   g_v);
    cudaGetSymbolAddress((void**)&pctx, g_ctx);
    cudaGetSymbolAddress((void**)&px,   g_x);
    cudaGetSymbolAddress((void**)&px1,  g_x1);
    cudaGetSymbolAddress((void**)&pff,  g_ff);
    cudaGetSymbolAddress((void**)&psin, g_sinf);
    cudaGetSymbolAddress((void**)&pcos, g_cosf);

    const int attn_smem = 4 * 64 * AP * (int)sizeof(float);   // 69632 B
    cudaFuncSetAttribute(attention_kernel,
                         cudaFuncAttributeMaxDynamicSharedMemorySize, attn_smem);

    // 1. RoPE factors
    rope_factors_kernel<<<TT, 256>>>(ropeA, ropeB, psin, pcos);

    // 2. QKV projections
    dim3 g1024(D_MODEL/128, MROWS/128);
    sgemm_kernel<<<g1024, 256>>>(tgt, Wq, bq, nullptr, pq, MROWS, D_MODEL, D_MODEL, 0);
    sgemm_kernel<<<g1024, 256>>>(tgt, Wk, bk, nullptr, pk, MROWS, D_MODEL, D_MODEL, 0);
    sgemm_kernel<<<g1024, 256>>>(tgt, Wv, bv, nullptr, pv, MROWS, D_MODEL, D_MODEL, 0);

    // 3. RoPE on q, k
    rope_apply_kernel<<<(MROWS*512)/256, 256>>>(pq, pk, psin, pcos);

    // 4. Attention
    dim3 ga(TT/64, BB*N_HEADS);
    attention_kernel<<<ga, 256, attn_smem>>>(pq, pk, pv, pctx);

    // 5. Output projection + residual
    sgemm_kernel<<<g1024, 256>>>(pctx, Wo, bo, tgt, px, MROWS, D_MODEL, D_MODEL, 0);

    // 6. LN1
    layernorm_kernel<<<MROWS, 256>>>(px, ln1g, ln1b, px1);

    // 7. FFN
    dim3 gff1(D_FF/128, MROWS/128);
    sgemm_kernel<<<gff1, 256>>>(px1, W1, b1, nullptr, pff, MROWS, D_FF, D_MODEL, 1);
    sgemm_kernel<<<g1024, 256>>>(pff, W2, b2, px1, px, MROWS, D_MODEL, D_FF, 0);

    // 8. LN2 -> output
    layernorm_kernel<<<MROWS, 256>>>(px, ln2g, ln2b, out);
}

// round 4
// speedup vs baseline: 1.5369x; 1.5369x over previous
#include <cuda_runtime.h>
#include <math.h>
#include <stdint.h>

#define D_MODEL 1024
#define N_HEADS 16
#define HEAD_DIM 64
#define D_FF 4096
#define ROPE_RANK 16
#define BB 2
#define TT 2048
#define MROWS (BB*TT)   // 4096

// ---------------- scratch (static device arrays; no cudaMalloc) ---------------
__device__ float g_q[MROWS*D_MODEL];
__device__ float g_k[MROWS*D_MODEL];
__device__ float g_v[MROWS*D_MODEL];
__device__ float g_ctx[MROWS*D_MODEL];
__device__ float g_x[MROWS*D_MODEL];
__device__ float g_x1[MROWS*D_MODEL];
__device__ float g_ff[MROWS*D_FF];
__device__ float g_sinf[TT*512];
__device__ float g_cosf[TT*512];
__device__ float g_w[12*1024*1024];   // tf32-rounded weights

// ================= helpers ====================================================
__device__ __forceinline__ uint32_t smem_u32(const void* p) {
    uint32_t a;
    asm("{ .reg .u64 t; cvta.to.shared.u64 t, %1; cvt.u32.u64 %0, t; }" : "=r"(a) : "l"(p));
    return a;
}
__device__ __forceinline__ uint32_t f2tf32(float f) {
    uint32_t u;
    asm("cvt.rna.tf32.f32 %0, %1;" : "=r"(u) : "f"(f));
    return u;
}
#define CP_ASYNC16(dst, src) \
    asm volatile("cp.async.cg.shared.global [%0], [%1], 16;" :: "r"(dst), "l"(src) : "memory")
#define CP_COMMIT() asm volatile("cp.async.commit_group;" ::: "memory")
#define CP_WAIT(n)  asm volatile("cp.async.wait_group %0;" :: "n"(n) : "memory")

#define MMA_TF32(d, a, b) \
    asm volatile("mma.sync.aligned.m16n8k8.row.col.f32.tf32.tf32.f32 " \
        "{%0,%1,%2,%3},{%4,%5,%6,%7},{%8,%9},{%0,%1,%2,%3};" \
        : "+f"((d)[0]), "+f"((d)[1]), "+f"((d)[2]), "+f"((d)[3]) \
        : "r"((a)[0]), "r"((a)[1]), "r"((a)[2]), "r"((a)[3]), "r"((b)[0]), "r"((b)[1]))

// ---------------- weight preconvert (fp32 -> tf32-rounded fp32) ---------------
__global__ void cvtw_kernel(const float* __restrict__ src, float* __restrict__ dst, int n4)
{
    int i = blockIdx.x * blockDim.x + threadIdx.x;
    if (i >= n4) return;
    float4 v = *(const float4*)&src[i*4];
    uint4 u = { f2tf32(v.x), f2tf32(v.y), f2tf32(v.z), f2tf32(v.w) };
    *(uint4*)&dst[i*4] = u;
}

// ---------------- tensor-core tf32 GEMM ---------------------------------------
// C[M,N] = A[M,K] @ W[K,N] (+bias, +resid, relu). CTA tile 128x128, BK=16.
// 256 thr = 8 warps, warp tile 32(M) x 64(N). W must be tf32-pre-rounded.
#define A_ST 20                       // floats per A smem row (pad: conflict-free frags)
#define B_ST 136                      // floats per B smem row
#define AS_BYTES (128*A_ST*4)         // 10240
#define BS_BYTES (16*B_ST*4)          // 8704
#define STAGE_BYTES (AS_BYTES + BS_BYTES)
#define GEMM_SMEM (2*STAGE_BYTES)     // 37888

__global__ __launch_bounds__(256, 2)
void mma_gemm(const float* __restrict__ A, const float* __restrict__ W,
              const float* __restrict__ bias, const float* __restrict__ resid,
              float* __restrict__ C, int M, int N, int K, int relu)
{
    extern __shared__ char smem[];
    uint32_t sbase = smem_u32(smem);

    int tid = threadIdx.x, lane = tid & 31, wid = tid >> 5;
    int m0 = blockIdx.y * 128, n0 = blockIdx.x * 128;
    int mw = (wid & 3) * 32, nw = (wid >> 2) * 64;
    int gid = lane >> 2, tg = lane & 3;

    float acc[2][8][4];
#pragma unroll
    for (int i = 0; i < 2; i++)
#pragma unroll
        for (int j = 0; j < 8; j++)
#pragma unroll
            for (int c = 0; c < 4; c++) acc[i][j][c] = 0.f;

    // load-index precompute
    int amA0 = tid >> 2,      akq0 = tid & 3;        // + iter*64 rows
    int bk0  = tid >> 5,      bc40 = tid & 31;       // + iter*8 rows

    float4 aReg[2];
    int T = K >> 4;

    // ---- prologue: kt = 0 ----
#pragma unroll
    for (int i = 0; i < 2; i++)
        aReg[i] = *(const float4*)&A[(size_t)(m0 + amA0 + i*64) * K + akq0 * 4];
#pragma unroll
    for (int i = 0; i < 2; i++) {
        int k = bk0 + i*8;
        CP_ASYNC16(sbase + AS_BYTES + (uint32_t)(k*B_ST + bc40*4)*4,
                   &W[(size_t)k * N + n0 + bc40*4]);
    }
    CP_COMMIT();
#pragma unroll
    for (int i = 0; i < 2; i++) {
        uint4 u = { f2tf32(aReg[i].x), f2tf32(aReg[i].y), f2tf32(aReg[i].z), f2tf32(aReg[i].w) };
        *(uint4*)(smem + ((amA0 + i*64)*A_ST + akq0*4)*4) = u;
    }

    for (int it = 0; it < T; it++) {
        int s = it & 1;
        uint32_t sStage  = s ? STAGE_BYTES : 0;
        uint32_t sStageN = s ? 0 : STAGE_BYTES;
        bool has_next = (it + 1 < T);
        if (has_next) {
            int kt = (it + 1) << 4;
#pragma unroll
            for (int i = 0; i < 2; i++)
                aReg[i] = *(const float4*)&A[(size_t)(m0 + amA0 + i*64) * K + kt + akq0 * 4];
#pragma unroll
            for (int i = 0; i < 2; i++) {
                int k = bk0 + i*8;
                CP_ASYNC16(sbase + sStageN + AS_BYTES + (uint32_t)(k*B_ST + bc40*4)*4,
                           &W[(size_t)(kt + k) * N + n0 + bc40*4]);
            }
            CP_COMMIT();
            CP_WAIT(1);
        } else {
            CP_WAIT(0);
        }
        __syncthreads();

        const uint32_t* As = (const uint32_t*)(smem + sStage);
        const uint32_t* Bs = (const uint32_t*)(smem + sStage + AS_BYTES);
#pragma unroll
        for (int kk = 0; kk < 16; kk += 8) {
            uint32_t af[2][4], bf[8][2];
#pragma unroll
            for (int mi = 0; mi < 2; mi++) {
                int r = mw + mi*16 + gid;
                af[mi][0] = As[r*A_ST + kk + tg];
                af[mi][1] = As[(r+8)*A_ST + kk + tg];
                af[mi][2] = As[r*A_ST + kk + tg + 4];
                af[mi][3] = As[(r+8)*A_ST + kk + tg + 4];
            }
#pragma unroll
            for (int nj = 0; nj < 8; nj++) {
                int c = nw + nj*8 + gid;
                bf[nj][0] = Bs[(kk + tg)*B_ST + c];
                bf[nj][1] = Bs[(kk + tg + 4)*B_ST + c];
            }
#pragma unroll
            for (int mi = 0; mi < 2; mi++)
#pragma unroll
                for (int nj = 0; nj < 8; nj++)
                    MMA_TF32(acc[mi][nj], af[mi], bf[nj]);
        }

        if (has_next) {
#pragma unroll
            for (int i = 0; i < 2; i++) {
                uint4 u = { f2tf32(aReg[i].x), f2tf32(aReg[i].y), f2tf32(aReg[i].z), f2tf32(aReg[i].w) };
                *(uint4*)(smem + sStageN + ((amA0 + i*64)*A_ST + akq0*4)*4) = u;
            }
        }
        __syncthreads();
    }

    // ---- epilogue ----
#pragma unroll
    for (int mi = 0; mi < 2; mi++) {
#pragma unroll
        for (int nj = 0; nj < 8; nj++) {
            int r = m0 + mw + mi*16 + gid;
            int c = n0 + nw + nj*8 + 2*tg;
            float2 bv = *(const float2*)&bias[c];
#pragma unroll
            for (int h = 0; h < 2; h++) {
                int rr = r + h*8;
                float2 v = { acc[mi][nj][2*h] + bv.x, acc[mi][nj][2*h+1] + bv.y };
                if (resid) {
                    float2 rv = *(const float2*)&resid[(size_t)rr * N + c];
                    v.x += rv.x; v.y += rv.y;
                }
                if (relu) { v.x = fmaxf(v.x, 0.f); v.y = fmaxf(v.y, 0.f); }
                *(float2*)&C[(size_t)rr * N + c] = v;
            }
        }
    }
}

// ---------------- RoPE factor precompute -------------------------------------
__global__ void rope_factors_kernel(const float* __restrict__ A,
                                    const float* __restrict__ Bm,
                                    float* __restrict__ sf, float* __restrict__ cf)
{
    int t = blockIdx.x;
    __shared__ float base[1024];
    __shared__ float tmp[ROPE_RANK];
    __shared__ float wred[8][ROPE_RANK];
    int tid = threadIdx.x;

    for (int j = tid; j < 1024; j += 256) {
        int i = j & 511;
        double theta_d = exp(-log(10000.0) * (double)i / 512.0);
        float theta = (float)theta_d;
        float ang = (float)t * theta;
        base[j] = (j < 512) ? sinf(ang) : cosf(ang);
    }
    __syncthreads();

    float loc[ROPE_RANK];
#pragma unroll
    for (int r = 0; r < ROPE_RANK; r++) loc[r] = 0.f;
    for (int j = tid; j < 1024; j += 256) {
        float bj = base[j];
#pragma unroll
        for (int r = 0; r < ROPE_RANK; r++) loc[r] += bj * A[j*ROPE_RANK + r];
    }
#pragma unroll
    for (int r = 0; r < ROPE_RANK; r++) {
#pragma unroll
        for (int off = 16; off; off >>= 1)
            loc[r] += __shfl_xor_sync(0xffffffffu, loc[r], off);
    }
    int warp = tid >> 5, lane = tid & 31;
    if (lane == 0) {
#pragma unroll
        for (int r = 0; r < ROPE_RANK; r++) wred[warp][r] = loc[r];
    }
    __syncthreads();
    if (tid < ROPE_RANK) {
        float s = 0.f;
#pragma unroll
        for (int w = 0; w < 8; w++) s += wred[w][tid];
        tmp[tid] = s;
    }
    __syncthreads();

    for (int d = tid; d < 1024; d += 256) {
        float s = 0.f;
#pragma unroll
        for (int r = 0; r < ROPE_RANK; r++) s += tmp[r] * Bm[r*1024 + d];
        float val = base[d] + s;
        if (d < 512) sf[t*512 + d]       = val;
        else         cf[t*512 + d - 512] = val;
    }
}

// ---------------- RoPE apply ---------------------------------------------------
__global__ void rope_apply_kernel(float* __restrict__ q, float* __restrict__ k,
                                  const float* __restrict__ sf, const float* __restrict__ cf)
{
    int idx = blockIdx.x * blockDim.x + threadIdx.x;
    if (idx >= MROWS*512) return;
    int p   = idx & 511;
    int row = idx >> 9;
    int t   = row & (TT-1);
    float s = sf[t*512 + p];
    float c = cf[t*512 + p];
    size_t base = (size_t)row*D_MODEL + 2*p;
    float qe = q[base], qo = q[base+1];
    q[base]   = qe*c - qo*s;
    q[base+1] = qe*s + qo*c;
    float ke = k[base], ko = k[base+1];
    k[base]   = ke*c - ko*s;
    k[base+1] = ke*s + ko*c;
}

// ---------------- Flash attention (fp32, no mask) ----------------------------
#define AP 68
__global__ __launch_bounds__(256)
void attention_kernel(const float* __restrict__ q, const float* __restrict__ k,
                      const float* __restrict__ v, float* __restrict__ ctx)
{
    extern __shared__ float sm[];
    float* Qs = sm;
    float* Ks = Qs + 64*AP;
    float* Vt = Ks + 64*AP;
    float* Ps = Vt + 64*AP;

    int qblk = blockIdx.x;
    int bh   = blockIdx.y;
    int b = bh >> 4, h = bh & 15;
    int tid = threadIdx.x;
    int tx = tid & 15, ty = tid >> 4;
    const float scale = 0.125f;

    int q0 = qblk * 64;
    size_t rowbase = (size_t)b * TT;
    int colbase = h * HEAD_DIM;

    for (int i = tid; i < 64*16; i += 256) {
        int r = i >> 4, c4 = (i & 15) * 4;
        float4 val = *(const float4*)&q[(rowbase + q0 + r)*D_MODEL + colbase + c4];
        val.x *= scale; val.y *= scale; val.z *= scale; val.w *= scale;
        *(float4*)&Qs[r*AP + c4] = val;
    }
    __syncthreads();

    float m_i[4], l_i[4], acc[4][4];
#pragma unroll
    for (int i = 0; i < 4; i++) {
        m_i[i] = -1e30f; l_i[i] = 0.f;
#pragma unroll
        for (int j = 0; j < 4; j++) acc[i][j] = 0.f;
    }

    for (int kt = 0; kt < TT; kt += 64) {
        for (int i = tid; i < 64*16; i += 256) {
            int r = i >> 4, c4 = (i & 15) * 4;
            *(float4*)&Ks[r*AP + c4] =
                *(const float4*)&k[(rowbase + kt + r)*D_MODEL + colbase + c4];
            float4 vv = *(const float4*)&v[(rowbase + kt + r)*D_MODEL + colbase + c4];
            Vt[(c4+0)*AP + r] = vv.x;
            Vt[(c4+1)*AP + r] = vv.y;
            Vt[(c4+2)*AP + r] = vv.z;
            Vt[(c4+3)*AP + r] = vv.w;
        }
        __syncthreads();

        float s[4][4];
#pragma unroll
        for (int i = 0; i < 4; i++)
#pragma unroll
            for (int j = 0; j < 4; j++) s[i][j] = 0.f;
#pragma unroll
        for (int d4 = 0; d4 < 16; d4++) {
            float4 a[4], bb[4];
#pragma unroll
            for (int i = 0; i < 4; i++) a[i]  = *(float4*)&Qs[(4*ty+i)*AP + d4*4];
#pragma unroll
            for (int j = 0; j < 4; j++) bb[j] = *(float4*)&Ks[(4*tx+j)*AP + d4*4];
#pragma unroll
            for (int i = 0; i < 4; i++)
#pragma unroll
                for (int j = 0; j < 4; j++)
                    s[i][j] += a[i].x*bb[j].x + a[i].y*bb[j].y + a[i].z*bb[j].z + a[i].w*bb[j].w;
        }

#pragma unroll
        for (int i = 0; i < 4; i++) {
            float tm = fmaxf(fmaxf(s[i][0], s[i][1]), fmaxf(s[i][2], s[i][3]));
#pragma unroll
            for (int off = 1; off < 16; off <<= 1)
                tm = fmaxf(tm, __shfl_xor_sync(0xffffffffu, tm, off));
            float m_new = fmaxf(m_i[i], tm);
            float corr  = __expf(m_i[i] - m_new);
            float rs = 0.f;
#pragma unroll
            for (int j = 0; j < 4; j++) {
                float p = __expf(s[i][j] - m_new);
                s[i][j] = p;
                rs += p;
            }
#pragma unroll
            for (int off = 1; off < 16; off <<= 1)
                rs += __shfl_xor_sync(0xffffffffu, rs, off);
            l_i[i] = l_i[i]*corr + rs;
            m_i[i] = m_new;
#pragma unroll
            for (int j = 0; j < 4; j++) {
                acc[i][j] *= corr;
                Ps[(4*ty+i)*AP + 4*tx+j] = s[i][j];
            }
        }
        __syncthreads();

#pragma unroll
        for (int k4 = 0; k4 < 16; k4++) {
            float4 p[4], vv[4];
#pragma unroll
            for (int i = 0; i < 4; i++) p[i]  = *(float4*)&Ps[(4*ty+i)*AP + k4*4];
#pragma unroll
            for (int j = 0; j < 4; j++) vv[j] = *(float4*)&Vt[(4*tx+j)*AP + k4*4];
#pragma unroll
            for (int i = 0; i < 4; i++)
#pragma unroll
                for (int j = 0; j < 4; j++)
                    acc[i][j] += p[i].x*vv[j].x + p[i].y*vv[j].y + p[i].z*vv[j].z + p[i].w*vv[j].w;
        }
        __syncthreads();
    }

#pragma unroll
    for (int i = 0; i < 4; i++) {
        float inv = 1.f / l_i[i];
#pragma unroll
        for (int j = 0; j < 4; j++)
            ctx[(rowbase + q0 + 4*ty + i)*D_MODEL + colbase + 4*tx + j] = acc[i][j] * inv;
    }
}

// ---------------- LayerNorm ---------------------------------------------------
__global__ __launch_bounds__(256)
void layernorm_kernel(const float* __restrict__ x, const float* __restrict__ g,
                      const float* __restrict__ bvec, float* __restrict__ out)
{
    int row = blockIdx.x;
    int tid = threadIdx.x;
    const float* xr = x + (size_t)row * D_MODEL;
    float4 v = *(const float4*)&xr[tid*4];
    float s  = v.x + v.y + v.z + v.w;
    float s2 = v.x*v.x + v.y*v.y + v.z*v.z + v.w*v.w;
#pragma unroll
    for (int off = 16; off; off >>= 1) {
        s  += __shfl_xor_sync(0xffffffffu, s,  off);
        s2 += __shfl_xor_sync(0xffffffffu, s2, off);
    }
    __shared__ float ws[8], ws2[8];
    __shared__ float smu, sinv;
    int warp = tid >> 5;
    if ((tid & 31) == 0) { ws[warp] = s; ws2[warp] = s2; }
    __syncthreads();
    if (tid == 0) {
        float a = 0.f, b2 = 0.f;
#pragma unroll
        for (int w = 0; w < 8; w++) { a += ws[w]; b2 += ws2[w]; }
        float mu  = a * (1.f/1024.f);
        float var = b2 * (1.f/1024.f) - mu*mu;
        smu = mu;
        sinv = rsqrtf(var + 1e-5f);
    }
    __syncthreads();
    float mu = smu, inv = sinv;
    float4 gg  = *(const float4*)&g[tid*4];
    float4 bb4 = *(const float4*)&bvec[tid*4];
    float4 o;
    o.x = (v.x - mu)*inv*gg.x + bb4.x;
    o.y = (v.y - mu)*inv*gg.y + bb4.y;
    o.z = (v.z - mu)*inv*gg.z + bb4.z;
    o.w = (v.w - mu)*inv*gg.w + bb4.w;
    *(float4*)&out[(size_t)row * D_MODEL + tid*4] = o;
}

// ---------------- launch ------------------------------------------------------
extern "C" void kernel_launch(void* const* d_in, const int* in_sizes, int n_in,
                              void* d_out, int out_size)
{
    const float* tgt  = (const float*)d_in[0];
    const float* Wq   = (const float*)d_in[1];
    const float* bq   = (const float*)d_in[2];
    const float* Wk   = (const float*)d_in[3];
    const float* bk   = (const float*)d_in[4];
    const float* Wv   = (const float*)d_in[5];
    const float* bv   = (const float*)d_in[6];
    const float* Wo   = (const float*)d_in[7];
    const float* bo   = (const float*)d_in[8];
    const float* W1   = (const float*)d_in[9];
    const float* b1   = (const float*)d_in[10];
    const float* W2   = (const float*)d_in[11];
    const float* b2   = (const float*)d_in[12];
    const float* ln1g = (const float*)d_in[13];
    const float* ln1b = (const float*)d_in[14];
    const float* ln2g = (const float*)d_in[15];
    const float* ln2b = (const float*)d_in[16];
    const float* ropeA = (const float*)d_in[17];
    const float* ropeB = (const float*)d_in[18];
    float* out = (float*)d_out;

    float *pq, *pk, *pv, *pctx, *px, *px1, *pff, *psin, *pcos, *pw;
    cudaGetSymbolAddress((void**)&pq,   g_q);
    cudaGetSymbolAddress((void**)&pk,   g_k);
    cudaGetSymbolAddress((void**)&pv,   g_v);
    cudaGetSymbolAddress((void**)&pctx, g_ctx);
    cudaGetSymbolAddress((void**)&px,   g_x);
    cudaGetSymbolAddress((void**)&px1,  g_x1);
    cudaGetSymbolAddress((void**)&pff,  g_ff);
    cudaGetSymbolAddress((void**)&psin, g_sinf);
    cudaGetSymbolAddress((void**)&pcos, g_cosf);
    cudaGetSymbolAddress((void**)&pw,   g_w);

    float* tWq = pw;
    float* tWk = pw + 1*1048576;
    float* tWv = pw + 2*1048576;
    float* tWo = pw + 3*1048576;
    float* tW1 = pw + 4*1048576;   // 4M
    float* tW2 = pw + 8*1048576;   // 4M

    const int attn_smem = 4 * 64 * AP * (int)sizeof(float);
    cudaFuncSetAttribute(attention_kernel,
                         cudaFuncAttributeMaxDynamicSharedMemorySize, attn_smem);

    // 0. weight preconvert to tf32-rounded fp32
    cvtw_kernel<<<1048576/4/256, 256>>>(Wq, tWq, 1048576/4);
    cvtw_kernel<<<1048576/4/256, 256>>>(Wk, tWk, 1048576/4);
    cvtw_kernel<<<1048576/4/256, 256>>>(Wv, tWv, 1048576/4);
    cvtw_kernel<<<1048576/4/256, 256>>>(Wo, tWo, 1048576/4);
    cvtw_kernel<<<4194304/4/256, 256>>>(W1, tW1, 4194304/4);
    cvtw_kernel<<<4194304/4/256, 256>>>(W2, tW2, 4194304/4);

    // 1. RoPE factors
    rope_factors_kernel<<<TT, 256>>>(ropeA, ropeB, psin, pcos);

    // 2. QKV projections (mma.sync tf32)
    dim3 g1024(D_MODEL/128, MROWS/128);
    mma_gemm<<<g1024, 256, GEMM_SMEM>>>(tgt, tWq, bq, nullptr, pq, MROWS, D_MODEL, D_MODEL, 0);
    mma_gemm<<<g1024, 256, GEMM_SMEM>>>(tgt, tWk, bk, nullptr, pk, MROWS, D_MODEL, D_MODEL, 0);
    mma_gemm<<<g1024, 256, GEMM_SMEM>>>(tgt, tWv, bv, nullptr, pv, MROWS, D_MODEL, D_MODEL, 0);

    // 3. RoPE on q, k
    rope_apply_kernel<<<(MROWS*512)/256, 256>>>(pq, pk, psin, pcos);

    // 4. Attention
    dim3 ga(TT/64, BB*N_HEADS);
    attention_kernel<<<ga, 256, attn_smem>>>(pq, pk, pv, pctx);

    // 5. Output projection + residual
    mma_gemm<<<g1024, 256, GEMM_SMEM>>>(pctx, tWo, bo, tgt, px, MROWS, D_MODEL, D_MODEL, 0);

    // 6. LN1
    layernorm_kernel<<<MROWS, 256>>>(px, ln1g, ln1b, px1);

    // 7. FFN
    dim3 gff1(D_FF/128, MROWS/128);
    mma_gemm<<<gff1, 256, GEMM_SMEM>>>(px1, tW1, b1, nullptr, pff, MROWS, D_FF, D_MODEL, 1);
    mma_gemm<<<g1024, 256, GEMM_SMEM>>>(pff, tW2, b2, px1, px, MROWS, D_MODEL, D_FF, 0);

    // 8. LN2 -> output
    layernorm_kernel<<<MROWS, 256>>>(px, ln2g, ln2b, out);
}

// round 8
// speedup vs baseline: 2.3657x; 1.5392x over previous
#include <cuda_runtime.h>
#include <math.h>
#include <stdint.h>

#define D_MODEL 1024
#define N_HEADS 16
#define HEAD_DIM 64
#define D_FF 4096
#define ROPE_RANK 16
#define BB 2
#define TT 2048
#define MROWS (BB*TT)   // 4096

// ---------------- scratch (static device arrays; no cudaMalloc) ---------------
__device__ float g_q[MROWS*D_MODEL];
__device__ float g_k[MROWS*D_MODEL];
__device__ float g_v[MROWS*D_MODEL];
__device__ float g_ctx[MROWS*D_MODEL];
__device__ float g_x[MROWS*D_MODEL];
__device__ float g_x1[MROWS*D_MODEL];
__device__ float g_ff[MROWS*D_FF];
__device__ float g_sinf[TT*512];
__device__ float g_cosf[TT*512];
__device__ float g_w[12*1024*1024];   // tf32-rounded weights

// ================= helpers ====================================================
__device__ __forceinline__ uint32_t smem_u32(const void* p) {
    uint32_t a;
    asm("{ .reg .u64 t; cvta.to.shared.u64 t, %1; cvt.u32.u64 %0, t; }" : "=r"(a) : "l"(p));
    return a;
}
__device__ __forceinline__ uint32_t f2tf32(float f) {
    uint32_t u;
    asm("cvt.rna.tf32.f32 %0, %1;" : "=r"(u) : "f"(f));
    return u;
}
#define CP_ASYNC16(dst, src) \
    asm volatile("cp.async.cg.shared.global [%0], [%1], 16;" :: "r"(dst), "l"(src) : "memory")
#define CP_COMMIT() asm volatile("cp.async.commit_group;" ::: "memory")
#define CP_WAIT(n)  asm volatile("cp.async.wait_group %0;" :: "n"(n) : "memory")

#define MMA_TF32(d, a, b) \
    asm volatile("mma.sync.aligned.m16n8k8.row.col.f32.tf32.tf32.f32 " \
        "{%0,%1,%2,%3},{%4,%5,%6,%7},{%8,%9},{%0,%1,%2,%3};" \
        : "+f"((d)[0]), "+f"((d)[1]), "+f"((d)[2]), "+f"((d)[3]) \
        : "r"((a)[0]), "r"((a)[1]), "r"((a)[2]), "r"((a)[3]), "r"((b)[0]), "r"((b)[1]))

// ---------------- weight preconvert (fp32 -> tf32-rounded fp32) ---------------
__global__ void cvtw_kernel(const float* __restrict__ src, float* __restrict__ dst, int n4)
{
    int i = blockIdx.x * blockDim.x + threadIdx.x;
    if (i >= n4) return;
    float4 v = *(const float4*)&src[i*4];
    uint4 u = { f2tf32(v.x), f2tf32(v.y), f2tf32(v.z), f2tf32(v.w) };
    *(uint4*)&dst[i*4] = u;
}

// ---------------- tensor-core tf32 GEMM ---------------------------------------
#define A_ST 20
#define B_ST 136
#define AS_BYTES (128*A_ST*4)
#define BS_BYTES (16*B_ST*4)
#define STAGE_BYTES (AS_BYTES + BS_BYTES)
#define GEMM_SMEM (2*STAGE_BYTES)

__global__ __launch_bounds__(256, 2)
void mma_gemm(const float* __restrict__ A, const float* __restrict__ W,
              const float* __restrict__ bias, const float* __restrict__ resid,
              float* __restrict__ C, int M, int N, int K, int relu)
{
    extern __shared__ char smem[];
    uint32_t sbase = smem_u32(smem);

    int tid = threadIdx.x, lane = tid & 31, wid = tid >> 5;
    int m0 = blockIdx.y * 128, n0 = blockIdx.x * 128;
    int mw = (wid & 3) * 32, nw = (wid >> 2) * 64;
    int gid = lane >> 2, tg = lane & 3;

    float acc[2][8][4];
#pragma unroll
    for (int i = 0; i < 2; i++)
#pragma unroll
        for (int j = 0; j < 8; j++)
#pragma unroll
            for (int c = 0; c < 4; c++) acc[i][j][c] = 0.f;

    int amA0 = tid >> 2,      akq0 = tid & 3;
    int bk0  = tid >> 5,      bc40 = tid & 31;

    float4 aReg[2];
    int T = K >> 4;

#pragma unroll
    for (int i = 0; i < 2; i++)
        aReg[i] = *(const float4*)&A[(size_t)(m0 + amA0 + i*64) * K + akq0 * 4];
#pragma unroll
    for (int i = 0; i < 2; i++) {
        int k = bk0 + i*8;
        CP_ASYNC16(sbase + AS_BYTES + (uint32_t)(k*B_ST + bc40*4)*4,
                   &W[(size_t)k * N + n0 + bc40*4]);
    }
    CP_COMMIT();
#pragma unroll
    for (int i = 0; i < 2; i++) {
        uint4 u = { f2tf32(aReg[i].x), f2tf32(aReg[i].y), f2tf32(aReg[i].z), f2tf32(aReg[i].w) };
        *(uint4*)(smem + ((amA0 + i*64)*A_ST + akq0*4)*4) = u;
    }

    for (int it = 0; it < T; it++) {
        int s = it & 1;
        uint32_t sStage  = s ? STAGE_BYTES : 0;
        uint32_t sStageN = s ? 0 : STAGE_BYTES;
        bool has_next = (it + 1 < T);
        if (has_next) {
            int kt = (it + 1) << 4;
#pragma unroll
            for (int i = 0; i < 2; i++)
                aReg[i] = *(const float4*)&A[(size_t)(m0 + amA0 + i*64) * K + kt + akq0 * 4];
#pragma unroll
            for (int i = 0; i < 2; i++) {
                int k = bk0 + i*8;
                CP_ASYNC16(sbase + sStageN + AS_BYTES + (uint32_t)(k*B_ST + bc40*4)*4,
                           &W[(size_t)(kt + k) * N + n0 + bc40*4]);
            }
            CP_COMMIT();
            CP_WAIT(1);
        } else {
            CP_WAIT(0);
        }
        __syncthreads();

        const uint32_t* As = (const uint32_t*)(smem + sStage);
        const uint32_t* Bs = (const uint32_t*)(smem + sStage + AS_BYTES);
#pragma unroll
        for (int kk = 0; kk < 16; kk += 8) {
            uint32_t af[2][4], bf[8][2];
#pragma unroll
            for (int mi = 0; mi < 2; mi++) {
                int r = mw + mi*16 + gid;
                af[mi][0] = As[r*A_ST + kk + tg];
                af[mi][1] = As[(r+8)*A_ST + kk + tg];
                af[mi][2] = As[r*A_ST + kk + tg + 4];
                af[mi][3] = As[(r+8)*A_ST + kk + tg + 4];
            }
#pragma unroll
            for (int nj = 0; nj < 8; nj++) {
                int c = nw + nj*8 + gid;
                bf[nj][0] = Bs[(kk + tg)*B_ST + c];
                bf[nj][1] = Bs[(kk + tg + 4)*B_ST + c];
            }
#pragma unroll
            for (int mi = 0; mi < 2; mi++)
#pragma unroll
                for (int nj = 0; nj < 8; nj++)
                    MMA_TF32(acc[mi][nj], af[mi], bf[nj]);
        }

        if (has_next) {
#pragma unroll
            for (int i = 0; i < 2; i++) {
                uint4 u = { f2tf32(aReg[i].x), f2tf32(aReg[i].y), f2tf32(aReg[i].z), f2tf32(aReg[i].w) };
                *(uint4*)(smem + sStageN + ((amA0 + i*64)*A_ST + akq0*4)*4) = u;
            }
        }
        __syncthreads();
    }

#pragma unroll
    for (int mi = 0; mi < 2; mi++) {
#pragma unroll
        for (int nj = 0; nj < 8; nj++) {
            int r = m0 + mw + mi*16 + gid;
            int c = n0 + nw + nj*8 + 2*tg;
            float2 bv = *(const float2*)&bias[c];
#pragma unroll
            for (int h = 0; h < 2; h++) {
                int rr = r + h*8;
                float2 v = { acc[mi][nj][2*h] + bv.x, acc[mi][nj][2*h+1] + bv.y };
                if (resid) {
                    float2 rv = *(const float2*)&resid[(size_t)rr * N + c];
                    v.x += rv.x; v.y += rv.y;
                }
                if (relu) { v.x = fmaxf(v.x, 0.f); v.y = fmaxf(v.y, 0.f); }
                *(float2*)&C[(size_t)rr * N + c] = v;
            }
        }
    }
}

// ---------------- RoPE factor precompute -------------------------------------
__global__ void rope_factors_kernel(const float* __restrict__ A,
                                    const float* __restrict__ Bm,
                                    float* __restrict__ sf, float* __restrict__ cf)
{
    int t = blockIdx.x;
    __shared__ float base[1024];
    __shared__ float tmp[ROPE_RANK];
    __shared__ float wred[8][ROPE_RANK];
    int tid = threadIdx.x;

    for (int j = tid; j < 1024; j += 256) {
        int i = j & 511;
        double theta_d = exp(-log(10000.0) * (double)i / 512.0);
        float theta = (float)theta_d;
        float ang = (float)t * theta;
        base[j] = (j < 512) ? sinf(ang) : cosf(ang);
    }
    __syncthreads();

    float loc[ROPE_RANK];
#pragma unroll
    for (int r = 0; r < ROPE_RANK; r++) loc[r] = 0.f;
    for (int j = tid; j < 1024; j += 256) {
        float bj = base[j];
#pragma unroll
        for (int r = 0; r < ROPE_RANK; r++) loc[r] += bj * A[j*ROPE_RANK + r];
    }
#pragma unroll
    for (int r = 0; r < ROPE_RANK; r++) {
#pragma unroll
        for (int off = 16; off; off >>= 1)
            loc[r] += __shfl_xor_sync(0xffffffffu, loc[r], off);
    }
    int warp = tid >> 5, lane = tid & 31;
    if (lane == 0) {
#pragma unroll
        for (int r = 0; r < ROPE_RANK; r++) wred[warp][r] = loc[r];
    }
    __syncthreads();
    if (tid < ROPE_RANK) {
        float s = 0.f;
#pragma unroll
        for (int w = 0; w < 8; w++) s += wred[w][tid];
        tmp[tid] = s;
    }
    __syncthreads();

    for (int d = tid; d < 1024; d += 256) {
        float s = 0.f;
#pragma unroll
        for (int r = 0; r < ROPE_RANK; r++) s += tmp[r] * Bm[r*1024 + d];
        float val = base[d] + s;
        if (d < 512) sf[t*512 + d]       = val;
        else         cf[t*512 + d - 512] = val;
    }
}

// ---------------- RoPE apply ---------------------------------------------------
__global__ void rope_apply_kernel(float* __restrict__ q, float* __restrict__ k,
                                  const float* __restrict__ sf, const float* __restrict__ cf)
{
    int idx = blockIdx.x * blockDim.x + threadIdx.x;
    if (idx >= MROWS*512) return;
    int p   = idx & 511;
    int row = idx >> 9;
    int t   = row & (TT-1);
    float s = sf[t*512 + p];
    float c = cf[t*512 + p];
    size_t base = (size_t)row*D_MODEL + 2*p;
    float qe = q[base], qo = q[base+1];
    q[base]   = qe*c - qo*s;
    q[base+1] = qe*s + qo*c;
    float ke = k[base], ko = k[base+1];
    k[base]   = ke*c - ko*s;
    k[base+1] = ke*s + ko*c;
}

// ---------------- Flash attention (tf32 mma.sync) -----------------------------
// 64q x 64k tiles, 128 threads (4 warps x 16 query rows), HEAD_DIM=64.
#define QS_ST 68
#define VS_ST 72
#define ATTN_SMEM ((3*64*QS_ST + 64*VS_ST)*4)   // 70656 B

__global__ __launch_bounds__(128)
void attn_mma_kernel(const float* __restrict__ q, const float* __restrict__ k,
                     const float* __restrict__ v, float* __restrict__ ctx)
{
    extern __shared__ float sm[];
    float* Qs = sm;                 // 64 x 68 (tf32, pre-scaled)
    float* Ks = Qs + 64*QS_ST;      // 64 x 68 (tf32)
    float* Ps = Ks + 64*QS_ST;      // 64 x 68 (tf32 probs)
    float* Vs = Ps + 64*QS_ST;      // 64 x 72 (tf32)

    int tid = threadIdx.x, lane = tid & 31, wid = tid >> 5;
    int gid = lane >> 2, tg = lane & 3;
    int qblk = blockIdx.x, bh = blockIdx.y;
    int b = bh >> 4, h = bh & 15;
    int q0 = qblk * 64;
    size_t rowbase = (size_t)b * TT;
    int colbase = h * HEAD_DIM;
    const float scale = 0.125f;

    // load Q tile (scaled, tf32-rounded)
    for (int i = tid; i < 64*16; i += 128) {
        int r = i >> 4, c4 = (i & 15) * 4;
        float4 val = *(const float4*)&q[(rowbase + q0 + r)*D_MODEL + colbase + c4];
        uint4 u = { f2tf32(val.x*scale), f2tf32(val.y*scale),
                    f2tf32(val.z*scale), f2tf32(val.w*scale) };
        *(uint4*)&Qs[r*QS_ST + c4] = u;
    }

    int qw = wid * 16;
    int r0 = qw + gid, r1 = r0 + 8;

    float m_i[2] = { -1e30f, -1e30f };
    float l_i[2] = { 0.f, 0.f };
    float oacc[8][4];
#pragma unroll
    for (int nj = 0; nj < 8; nj++)
#pragma unroll
        for (int c = 0; c < 4; c++) oacc[nj][c] = 0.f;

    for (int kt = 0; kt < TT; kt += 64) {
        __syncthreads();   // prior-iter Ks/Vs reads done (also orders Qs on iter 0)
        for (int i = tid; i < 64*16; i += 128) {
            int r = i >> 4, c4 = (i & 15) * 4;
            float4 kv = *(const float4*)&k[(rowbase + kt + r)*D_MODEL + colbase + c4];
            uint4 uk = { f2tf32(kv.x), f2tf32(kv.y), f2tf32(kv.z), f2tf32(kv.w) };
            *(uint4*)&Ks[r*QS_ST + c4] = uk;
            float4 vv = *(const float4*)&v[(rowbase + kt + r)*D_MODEL + colbase + c4];
            uint4 uv = { f2tf32(vv.x), f2tf32(vv.y), f2tf32(vv.z), f2tf32(vv.w) };
            *(uint4*)&Vs[r*VS_ST + c4] = uv;
        }
        __syncthreads();

        // ---- S = Q K^T (m16 x n64 x k64 per warp) ----
        float sacc[8][4];
#pragma unroll
        for (int nj = 0; nj < 8; nj++)
#pragma unroll
            for (int c = 0; c < 4; c++) sacc[nj][c] = 0.f;
#pragma unroll
        for (int kk = 0; kk < 64; kk += 8) {
            uint32_t af[4];
            af[0] = __float_as_uint(Qs[r0*QS_ST + kk + tg]);
            af[1] = __float_as_uint(Qs[r1*QS_ST + kk + tg]);
            af[2] = __float_as_uint(Qs[r0*QS_ST + kk + tg + 4]);
            af[3] = __float_as_uint(Qs[r1*QS_ST + kk + tg + 4]);
#pragma unroll
            for (int nj = 0; nj < 8; nj++) {
                uint32_t bf[2];
                bf[0] = __float_as_uint(Ks[(nj*8 + gid)*QS_ST + kk + tg]);
                bf[1] = __float_as_uint(Ks[(nj*8 + gid)*QS_ST + kk + tg + 4]);
                MMA_TF32(sacc[nj], af, bf);
            }
        }

        // ---- online softmax (rows r0, r1; stats across 4-lane tg group) ----
#pragma unroll
        for (int rh = 0; rh < 2; rh++) {
            float tm = -1e30f;
#pragma unroll
            for (int nj = 0; nj < 8; nj++)
                tm = fmaxf(tm, fmaxf(sacc[nj][2*rh], sacc[nj][2*rh+1]));
            tm = fmaxf(tm, __shfl_xor_sync(0xffffffffu, tm, 1));
            tm = fmaxf(tm, __shfl_xor_sync(0xffffffffu, tm, 2));
            float m_new = fmaxf(m_i[rh], tm);
            float corr  = __expf(m_i[rh] - m_new);
            float rs = 0.f;
            int row = rh ? r1 : r0;
#pragma unroll
            for (int nj = 0; nj < 8; nj++) {
                float p0 = __expf(sacc[nj][2*rh]   - m_new);
                float p1 = __expf(sacc[nj][2*rh+1] - m_new);
                rs += p0 + p1;
                uint2 pu = { f2tf32(p0), f2tf32(p1) };
                *(uint2*)&Ps[row*QS_ST + nj*8 + 2*tg] = pu;
                oacc[nj][2*rh]   *= corr;
                oacc[nj][2*rh+1] *= corr;
            }
            rs += __shfl_xor_sync(0xffffffffu, rs, 1);
            rs += __shfl_xor_sync(0xffffffffu, rs, 2);
            l_i[rh] = l_i[rh]*corr + rs;
            m_i[rh] = m_new;
        }
        __syncwarp();

        // ---- O += P V (m16 x n64 x k64 per warp) ----
#pragma unroll
        for (int kk = 0; kk < 64; kk += 8) {
            uint32_t af[4];
            af[0] = __float_as_uint(Ps[r0*QS_ST + kk + tg]);
            af[1] = __float_as_uint(Ps[r1*QS_ST + kk + tg]);
            af[2] = __float_as_uint(Ps[r0*QS_ST + kk + tg + 4]);
            af[3] = __float_as_uint(Ps[r1*QS_ST + kk + tg + 4]);
#pragma unroll
            for (int nj = 0; nj < 8; nj++) {
                uint32_t bf[2];
                bf[0] = __float_as_uint(Vs[(kk + tg)*VS_ST + nj*8 + gid]);
                bf[1] = __float_as_uint(Vs[(kk + tg + 4)*VS_ST + nj*8 + gid]);
                MMA_TF32(oacc[nj], af, bf);
            }
        }
    }

    float inv0 = 1.f / l_i[0], inv1 = 1.f / l_i[1];
#pragma unroll
    for (int nj = 0; nj < 8; nj++) {
        int c = colbase + nj*8 + 2*tg;
        float2 o0 = { oacc[nj][0]*inv0, oacc[nj][1]*inv0 };
        float2 o1 = { oacc[nj][2]*inv1, oacc[nj][3]*inv1 };
        *(float2*)&ctx[(rowbase + q0 + r0)*D_MODEL + c] = o0;
        *(float2*)&ctx[(rowbase + q0 + r1)*D_MODEL + c] = o1;
    }
}

// ---------------- LayerNorm ---------------------------------------------------
__global__ __launch_bounds__(256)
void layernorm_kernel(const float* __restrict__ x, const float* __restrict__ g,
                      const float* __restrict__ bvec, float* __restrict__ out)
{
    int row = blockIdx.x;
    int tid = threadIdx.x;
    const float* xr = x + (size_t)row * D_MODEL;
    float4 v = *(const float4*)&xr[tid*4];
    float s  = v.x + v.y + v.z + v.w;
    float s2 = v.x*v.x + v.y*v.y + v.z*v.z + v.w*v.w;
#pragma unroll
    for (int off = 16; off; off >>= 1) {
        s  += __shfl_xor_sync(0xffffffffu, s,  off);
        s2 += __shfl_xor_sync(0xffffffffu, s2, off);
    }
    __shared__ float ws[8], ws2[8];
    __shared__ float smu, sinv;
    int warp = tid >> 5;
    if ((tid & 31) == 0) { ws[warp] = s; ws2[warp] = s2; }
    __syncthreads();
    if (tid == 0) {
        float a = 0.f, b2 = 0.f;
#pragma unroll
        for (int w = 0; w < 8; w++) { a += ws[w]; b2 += ws2[w]; }
        float mu  = a * (1.f/1024.f);
        float var = b2 * (1.f/1024.f) - mu*mu;
        smu = mu;
        sinv = rsqrtf(var + 1e-5f);
    }
    __syncthreads();
    float mu = smu, inv = sinv;
    float4 gg  = *(const float4*)&g[tid*4];
    float4 bb4 = *(const float4*)&bvec[tid*4];
    float4 o;
    o.x = (v.x - mu)*inv*gg.x + bb4.x;
    o.y = (v.y - mu)*inv*gg.y + bb4.y;
    o.z = (v.z - mu)*inv*gg.z + bb4.z;
    o.w = (v.w - mu)*inv*gg.w + bb4.w;
    *(float4*)&out[(size_t)row * D_MODEL + tid*4] = o;
}

// ---------------- launch ------------------------------------------------------
extern "C" void kernel_launch(void* const* d_in, const int* in_sizes, int n_in,
                              void* d_out, int out_size)
{
    const float* tgt  = (const float*)d_in[0];
    const float* Wq   = (const float*)d_in[1];
    const float* bq   = (const float*)d_in[2];
    const float* Wk   = (const float*)d_in[3];
    const float* bk   = (const float*)d_in[4];
    const float* Wv   = (const float*)d_in[5];
    const float* bv   = (const float*)d_in[6];
    const float* Wo   = (const float*)d_in[7];
    const float* bo   = (const float*)d_in[8];
    const float* W1   = (const float*)d_in[9];
    const float* b1   = (const float*)d_in[10];
    const float* W2   = (const float*)d_in[11];
    const float* b2   = (const float*)d_in[12];
    const float* ln1g = (const float*)d_in[13];
    const float* ln1b = (const float*)d_in[14];
    const float* ln2g = (const float*)d_in[15];
    const float* ln2b = (const float*)d_in[16];
    const float* ropeA = (const float*)d_in[17];
    const float* ropeB = (const float*)d_in[18];
    float* out = (float*)d_out;

    float *pq, *pk, *pv, *pctx, *px, *px1, *pff, *psin, *pcos, *pw;
    cudaGetSymbolAddress((void**)&pq,   g_q);
    cudaGetSymbolAddress((void**)&pk,   g_k);
    cudaGetSymbolAddress((void**)&pv,   g_v);
    cudaGetSymbolAddress((void**)&pctx, g_ctx);
    cudaGetSymbolAddress((void**)&px,   g_x);
    cudaGetSymbolAddress((void**)&px1,  g_x1);
    cudaGetSymbolAddress((void**)&pff,  g_ff);
    cudaGetSymbolAddress((void**)&psin, g_sinf);
    cudaGetSymbolAddress((void**)&pcos, g_cosf);
    cudaGetSymbolAddress((void**)&pw,   g_w);

    float* tWq = pw;
    float* tWk = pw + 1*1048576;
    float* tWv = pw + 2*1048576;
    float* tWo = pw + 3*1048576;
    float* tW1 = pw + 4*1048576;
    float* tW2 = pw + 8*1048576;

    cudaFuncSetAttribute(attn_mma_kernel,
                         cudaFuncAttributeMaxDynamicSharedMemorySize, ATTN_SMEM);

    // 0. weight preconvert to tf32-rounded fp32
    cvtw_kernel<<<1048576/4/256, 256>>>(Wq, tWq, 1048576/4);
    cvtw_kernel<<<1048576/4/256, 256>>>(Wk, tWk, 1048576/4);
    cvtw_kernel<<<1048576/4/256, 256>>>(Wv, tWv, 1048576/4);
    cvtw_kernel<<<1048576/4/256, 256>>>(Wo, tWo, 1048576/4);
    cvtw_kernel<<<4194304/4/256, 256>>>(W1, tW1, 4194304/4);
    cvtw_kernel<<<4194304/4/256, 256>>>(W2, tW2, 4194304/4);

    // 1. RoPE factors
    rope_factors_kernel<<<TT, 256>>>(ropeA, ropeB, psin, pcos);

    // 2. QKV projections
    dim3 g1024(D_MODEL/128, MROWS/128);
    mma_gemm<<<g1024, 256, GEMM_SMEM>>>(tgt, tWq, bq, nullptr, pq, MROWS, D_MODEL, D_MODEL, 0);
    mma_gemm<<<g1024, 256, GEMM_SMEM>>>(tgt, tWk, bk, nullptr, pk, MROWS, D_MODEL, D_MODEL, 0);
    mma_gemm<<<g1024, 256, GEMM_SMEM>>>(tgt, tWv, bv, nullptr, pv, MROWS, D_MODEL, D_MODEL, 0);

    // 3. RoPE on q, k
    rope_apply_kernel<<<(MROWS*512)/256, 256>>>(pq, pk, psin, pcos);

    // 4. Attention (tensor core)
    dim3 ga(TT/64, BB*N_HEADS);
    attn_mma_kernel<<<ga, 128, ATTN_SMEM>>>(pq, pk, pv, pctx);

    // 5. Output projection + residual
    mma_gemm<<<g1024, 256, GEMM_SMEM>>>(pctx, tWo, bo, tgt, px, MROWS, D_MODEL, D_MODEL, 0);

    // 6. LN1
    layernorm_kernel<<<MROWS, 256>>>(px, ln1g, ln1b, px1);

    // 7. FFN
    dim3 gff1(D_FF/128, MROWS/128);
    mma_gemm<<<gff1, 256, GEMM_SMEM>>>(px1, tW1, b1, nullptr, pff, MROWS, D_FF, D_MODEL, 1);
    mma_gemm<<<g1024, 256, GEMM_SMEM>>>(pff, tW2, b2, px1, px, MROWS, D_MODEL, D_FF, 0);

    // 8. LN2 -> output
    layernorm_kernel<<<MROWS, 256>>>(px, ln2g, ln2b, out);
}

// round 10
// speedup vs baseline: 3.6523x; 1.5439x over previous
#include <cuda_runtime.h>
#include <math.h>
#include <stdint.h>

#define D_MODEL 1024
#define N_HEADS 16
#define HEAD_DIM 64
#define D_FF 4096
#define ROPE_RANK 16
#define BB 2
#define TT 2048
#define MROWS (BB*TT)   // 4096
#define QKV_N 3072

// ---------------- scratch (static device arrays; no cudaMalloc) ---------------
__device__ float g_qkv[MROWS*QKV_N];
__device__ float g_ctx[MROWS*D_MODEL];
__device__ float g_x[MROWS*D_MODEL];
__device__ float g_x1[MROWS*D_MODEL];
__device__ float g_ff[MROWS*D_FF];
__device__ float g_sinf[TT*512];
__device__ float g_cosf[TT*512];
__device__ float g_w[12*1024*1024];   // tf32-rounded weights
__device__ float g_bqkv[QKV_N];

// ================= helpers ====================================================
__device__ __forceinline__ uint32_t smem_u32(const void* p) {
    uint32_t a;
    asm("{ .reg .u64 t; cvta.to.shared.u64 t, %1; cvt.u32.u64 %0, t; }" : "=r"(a) : "l"(p));
    return a;
}
__device__ __forceinline__ uint32_t f2tf32(float f) {
    uint32_t u;
    asm("cvt.rna.tf32.f32 %0, %1;" : "=r"(u) : "f"(f));
    return u;
}
#define CP_ASYNC16(dst, src) \
    asm volatile("cp.async.cg.shared.global [%0], [%1], 16;" :: "r"(dst), "l"(src) : "memory")
#define CP_COMMIT() asm volatile("cp.async.commit_group;" ::: "memory")
#define CP_WAIT(n)  asm volatile("cp.async.wait_group %0;" :: "n"(n) : "memory")

#define MMA_TF32(d, a, b) \
    asm volatile("mma.sync.aligned.m16n8k8.row.col.f32.tf32.tf32.f32 " \
        "{%0,%1,%2,%3},{%4,%5,%6,%7},{%8,%9},{%0,%1,%2,%3};" \
        : "+f"((d)[0]), "+f"((d)[1]), "+f"((d)[2]), "+f"((d)[3]) \
        : "r"((a)[0]), "r"((a)[1]), "r"((a)[2]), "r"((a)[3]), "r"((b)[0]), "r"((b)[1]))

// ---------------- weight preconvert (fp32 -> tf32-rounded fp32) ---------------
__global__ void cvtw_kernel(const float* __restrict__ src, float* __restrict__ dst, int n4)
{
    int i = blockIdx.x * blockDim.x + threadIdx.x;
    if (i >= n4) return;
    float4 v = *(const float4*)&src[i*4];
    uint4 u = { f2tf32(v.x), f2tf32(v.y), f2tf32(v.z), f2tf32(v.w) };
    *(uint4*)&dst[i*4] = u;
}

// place a 1024-wide weight into a 3072-wide packed matrix at column offset
__global__ void cvtw_place_kernel(const float* __restrict__ src, float* __restrict__ dst,
                                  int n4, int coloff)
{
    int i = blockIdx.x * blockDim.x + threadIdx.x;
    if (i >= n4) return;
    int row = (i*4) >> 10;         // src width 1024
    int col = (i*4) & 1023;
    float4 v = *(const float4*)&src[i*4];
    uint4 u = { f2tf32(v.x), f2tf32(v.y), f2tf32(v.z), f2tf32(v.w) };
    *(uint4*)&dst[(size_t)row * QKV_N + coloff + col] = u;
}

__global__ void pack_bias_kernel(const float* __restrict__ bq, const float* __restrict__ bk,
                                 const float* __restrict__ bv, float* __restrict__ dst)
{
    int i = blockIdx.x * blockDim.x + threadIdx.x;
    if (i >= QKV_N) return;
    float v = (i < 1024) ? bq[i] : (i < 2048 ? bk[i-1024] : bv[i-2048]);
    dst[i] = v;
}

// ---------------- tensor-core tf32 GEMM ---------------------------------------
// CTA tile 128x128, BK=16, 128 threads = 4 warps (2x2), warp tile 64x64.
#define A_ST 20
#define B_ST 136
#define AS_BYTES (128*A_ST*4)         // 10240
#define BS_BYTES (16*B_ST*4)          // 8704
#define STAGE_BYTES (AS_BYTES + BS_BYTES)
#define GEMM_SMEM (2*STAGE_BYTES)     // 37888

__global__ __launch_bounds__(128, 2)
void mma_gemm(const float* __restrict__ A, const float* __restrict__ W,
              const float* __restrict__ bias, const float* __restrict__ resid,
              float* __restrict__ C, int M, int N, int K, int relu)
{
    extern __shared__ char smem[];
    uint32_t sbase = smem_u32(smem);

    int tid = threadIdx.x, lane = tid & 31, wid = tid >> 5;
    int m0 = blockIdx.y * 128, n0 = blockIdx.x * 128;
    int mw = (wid & 1) * 64, nw = (wid >> 1) * 64;
    int gid = lane >> 2, tg = lane & 3;

    float acc[4][8][4];
#pragma unroll
    for (int i = 0; i < 4; i++)
#pragma unroll
        for (int j = 0; j < 8; j++)
#pragma unroll
            for (int c = 0; c < 4; c++) acc[i][j][c] = 0.f;

    // A: 128 rows x 16 cols; each thread 4 float4 (rows ar+32i, col ac)
    int ar = tid >> 2, ac = (tid & 3) * 4;
    // B: 16 rows x 128 cols; each thread 4 cp.async (rows bk0+4i)
    int bk0 = tid >> 5, bc4 = (tid & 31) * 4;

    float4 aReg[4];
    int T = K >> 4;

    // ---- prologue: stage 0 ----
#pragma unroll
    for (int i = 0; i < 4; i++)
        aReg[i] = *(const float4*)&A[(size_t)(m0 + ar + i*32) * K + ac];
#pragma unroll
    for (int i = 0; i < 4; i++) {
        int k = bk0 + i*4;
        CP_ASYNC16(sbase + AS_BYTES + (uint32_t)(k*B_ST + bc4)*4,
                   &W[(size_t)k * N + n0 + bc4]);
    }
    CP_COMMIT();
#pragma unroll
    for (int i = 0; i < 4; i++) {
        uint4 u = { f2tf32(aReg[i].x), f2tf32(aReg[i].y), f2tf32(aReg[i].z), f2tf32(aReg[i].w) };
        *(uint4*)(smem + ((ar + i*32)*A_ST + ac)*4) = u;
    }

    for (int it = 0; it < T; it++) {
        int s = it & 1;
        uint32_t sStage  = s ? STAGE_BYTES : 0;
        uint32_t sStageN = s ? 0 : STAGE_BYTES;
        bool has_next = (it + 1 < T);
        if (has_next) {
            int kt = (it + 1) << 4;
#pragma unroll
            for (int i = 0; i < 4; i++)
                aReg[i] = *(const float4*)&A[(size_t)(m0 + ar + i*32) * K + kt + ac];
#pragma unroll
            for (int i = 0; i < 4; i++) {
                int k = bk0 + i*4;
                CP_ASYNC16(sbase + sStageN + AS_BYTES + (uint32_t)(k*B_ST + bc4)*4,
                           &W[(size_t)(kt + k) * N + n0 + bc4]);
            }
            CP_COMMIT();
            CP_WAIT(1);
        } else {
            CP_WAIT(0);
        }
        __syncthreads();

        const uint32_t* As = (const uint32_t*)(smem + sStage);
        const uint32_t* Bs = (const uint32_t*)(smem + sStage + AS_BYTES);
#pragma unroll
        for (int kk = 0; kk < 16; kk += 8) {
            uint32_t af[4][4], bf[8][2];
#pragma unroll
            for (int mi = 0; mi < 4; mi++) {
                int r = mw + mi*16 + gid;
                af[mi][0] = As[r*A_ST + kk + tg];
                af[mi][1] = As[(r+8)*A_ST + kk + tg];
                af[mi][2] = As[r*A_ST + kk + tg + 4];
                af[mi][3] = As[(r+8)*A_ST + kk + tg + 4];
            }
#pragma unroll
            for (int nj = 0; nj < 8; nj++) {
                int c = nw + nj*8 + gid;
                bf[nj][0] = Bs[(kk + tg)*B_ST + c];
                bf[nj][1] = Bs[(kk + tg + 4)*B_ST + c];
            }
#pragma unroll
            for (int mi = 0; mi < 4; mi++)
#pragma unroll
                for (int nj = 0; nj < 8; nj++)
                    MMA_TF32(acc[mi][nj], af[mi], bf[nj]);
        }

        if (has_next) {
#pragma unroll
            for (int i = 0; i < 4; i++) {
                uint4 u = { f2tf32(aReg[i].x), f2tf32(aReg[i].y), f2tf32(aReg[i].z), f2tf32(aReg[i].w) };
                *(uint4*)(smem + sStageN + ((ar + i*32)*A_ST + ac)*4) = u;
            }
        }
        __syncthreads();
    }

    // ---- epilogue ----
#pragma unroll
    for (int mi = 0; mi < 4; mi++) {
#pragma unroll
        for (int nj = 0; nj < 8; nj++) {
            int r = m0 + mw + mi*16 + gid;
            int c = n0 + nw + nj*8 + 2*tg;
            float2 bv = *(const float2*)&bias[c];
#pragma unroll
            for (int h = 0; h < 2; h++) {
                int rr = r + h*8;
                float2 v = { acc[mi][nj][2*h] + bv.x, acc[mi][nj][2*h+1] + bv.y };
                if (resid) {
                    float2 rv = *(const float2*)&resid[(size_t)rr * N + c];
                    v.x += rv.x; v.y += rv.y;
                }
                if (relu) { v.x = fmaxf(v.x, 0.f); v.y = fmaxf(v.y, 0.f); }
                *(float2*)&C[(size_t)rr * N + c] = v;
            }
        }
    }
}

// ---------------- RoPE factor precompute -------------------------------------
__global__ void rope_factors_kernel(const float* __restrict__ A,
                                    const float* __restrict__ Bm,
                                    float* __restrict__ sf, float* __restrict__ cf)
{
    int t = blockIdx.x;
    __shared__ float base[1024];
    __shared__ float tmp[ROPE_RANK];
    __shared__ float wred[8][ROPE_RANK];
    int tid = threadIdx.x;

    for (int j = tid; j < 1024; j += 256) {
        int i = j & 511;
        double theta_d = exp(-log(10000.0) * (double)i / 512.0);
        float theta = (float)theta_d;
        float ang = (float)t * theta;
        base[j] = (j < 512) ? sinf(ang) : cosf(ang);
    }
    __syncthreads();

    float loc[ROPE_RANK];
#pragma unroll
    for (int r = 0; r < ROPE_RANK; r++) loc[r] = 0.f;
    for (int j = tid; j < 1024; j += 256) {
        float bj = base[j];
#pragma unroll
        for (int r = 0; r < ROPE_RANK; r++) loc[r] += bj * A[j*ROPE_RANK + r];
    }
#pragma unroll
    for (int r = 0; r < ROPE_RANK; r++) {
#pragma unroll
        for (int off = 16; off; off >>= 1)
            loc[r] += __shfl_xor_sync(0xffffffffu, loc[r], off);
    }
    int warp = tid >> 5, lane = tid & 31;
    if (lane == 0) {
#pragma unroll
        for (int r = 0; r < ROPE_RANK; r++) wred[warp][r] = loc[r];
    }
    __syncthreads();
    if (tid < ROPE_RANK) {
        float s = 0.f;
#pragma unroll
        for (int w = 0; w < 8; w++) s += wred[w][tid];
        tmp[tid] = s;
    }
    __syncthreads();

    for (int d = tid; d < 1024; d += 256) {
        float s = 0.f;
#pragma unroll
        for (int r = 0; r < ROPE_RANK; r++) s += tmp[r] * Bm[r*1024 + d];
        float val = base[d] + s;
        if (d < 512) sf[t*512 + d]       = val;
        else         cf[t*512 + d - 512] = val;
    }
}

// ---------------- RoPE apply (q,k inside packed qkv) ---------------------------
__global__ void rope_apply_kernel(float* __restrict__ qkv,
                                  const float* __restrict__ sf, const float* __restrict__ cf)
{
    int idx = blockIdx.x * blockDim.x + threadIdx.x;
    if (idx >= MROWS*512) return;
    int p   = idx & 511;
    int row = idx >> 9;
    int t   = row & (TT-1);
    float s = sf[t*512 + p];
    float c = cf[t*512 + p];
    size_t base = (size_t)row*QKV_N + 2*p;
    float qe = qkv[base], qo = qkv[base+1];
    qkv[base]   = qe*c - qo*s;
    qkv[base+1] = qe*s + qo*c;
    float ke = qkv[base+1024], ko = qkv[base+1025];
    qkv[base+1024] = ke*c - ko*s;
    qkv[base+1025] = ke*s + ko*c;
}

// ---------------- Flash attention (tf32 mma.sync) -----------------------------
// 64q x 64k tiles, 128 threads (4 warps x 16 query rows), HEAD_DIM=64.
#define QS_ST 68
#define VS_ST 72
#define ATTN_SMEM ((3*64*QS_ST + 64*VS_ST)*4)   // 70656 B

__global__ __launch_bounds__(128)
void attn_mma_kernel(const float* __restrict__ q, const float* __restrict__ k,
                     const float* __restrict__ v, int ld, float* __restrict__ ctx)
{
    extern __shared__ float sm[];
    float* Qs = sm;
    float* Ks = Qs + 64*QS_ST;
    float* Ps = Ks + 64*QS_ST;
    float* Vs = Ps + 64*QS_ST;

    int tid = threadIdx.x, lane = tid & 31, wid = tid >> 5;
    int gid = lane >> 2, tg = lane & 3;
    int qblk = blockIdx.x, bh = blockIdx.y;
    int b = bh >> 4, h = bh & 15;
    int q0 = qblk * 64;
    size_t rowbase = (size_t)b * TT;
    int colbase = h * HEAD_DIM;
    const float scale = 0.125f;

    for (int i = tid; i < 64*16; i += 128) {
        int r = i >> 4, c4 = (i & 15) * 4;
        float4 val = *(const float4*)&q[(rowbase + q0 + r)*ld + colbase + c4];
        uint4 u = { f2tf32(val.x*scale), f2tf32(val.y*scale),
                    f2tf32(val.z*scale), f2tf32(val.w*scale) };
        *(uint4*)&Qs[r*QS_ST + c4] = u;
    }

    int qw = wid * 16;
    int r0 = qw + gid, r1 = r0 + 8;

    float m_i[2] = { -1e30f, -1e30f };
    float l_i[2] = { 0.f, 0.f };
    float oacc[8][4];
#pragma unroll
    for (int nj = 0; nj < 8; nj++)
#pragma unroll
        for (int c = 0; c < 4; c++) oacc[nj][c] = 0.f;

    for (int kt = 0; kt < TT; kt += 64) {
        __syncthreads();
        for (int i = tid; i < 64*16; i += 128) {
            int r = i >> 4, c4 = (i & 15) * 4;
            float4 kv = *(const float4*)&k[(rowbase + kt + r)*ld + colbase + c4];
            uint4 uk = { f2tf32(kv.x), f2tf32(kv.y), f2tf32(kv.z), f2tf32(kv.w) };
            *(uint4*)&Ks[r*QS_ST + c4] = uk;
            float4 vv = *(const float4*)&v[(rowbase + kt + r)*ld + colbase + c4];
            uint4 uv = { f2tf32(vv.x), f2tf32(vv.y), f2tf32(vv.z), f2tf32(vv.w) };
            *(uint4*)&Vs[r*VS_ST + c4] = uv;
        }
        __syncthreads();

        float sacc[8][4];
#pragma unroll
        for (int nj = 0; nj < 8; nj++)
#pragma unroll
            for (int c = 0; c < 4; c++) sacc[nj][c] = 0.f;
#pragma unroll
        for (int kk = 0; kk < 64; kk += 8) {
            uint32_t af[4];
            af[0] = __float_as_uint(Qs[r0*QS_ST + kk + tg]);
            af[1] = __float_as_uint(Qs[r1*QS_ST + kk + tg]);
            af[2] = __float_as_uint(Qs[r0*QS_ST + kk + tg + 4]);
            af[3] = __float_as_uint(Qs[r1*QS_ST + kk + tg + 4]);
#pragma unroll
            for (int nj = 0; nj < 8; nj++) {
                uint32_t bf[2];
                bf[0] = __float_as_uint(Ks[(nj*8 + gid)*QS_ST + kk + tg]);
                bf[1] = __float_as_uint(Ks[(nj*8 + gid)*QS_ST + kk + tg + 4]);
                MMA_TF32(sacc[nj], af, bf);
            }
        }

#pragma unroll
        for (int rh = 0; rh < 2; rh++) {
            float tm = -1e30f;
#pragma unroll
            for (int nj = 0; nj < 8; nj++)
                tm = fmaxf(tm, fmaxf(sacc[nj][2*rh], sacc[nj][2*rh+1]));
            tm = fmaxf(tm, __shfl_xor_sync(0xffffffffu, tm, 1));
            tm = fmaxf(tm, __shfl_xor_sync(0xffffffffu, tm, 2));
            float m_new = fmaxf(m_i[rh], tm);
            float corr  = __expf(m_i[rh] - m_new);
            float rs = 0.f;
            int row = rh ? r1 : r0;
#pragma unroll
            for (int nj = 0; nj < 8; nj++) {
                float p0 = __expf(sacc[nj][2*rh]   - m_new);
                float p1 = __expf(sacc[nj][2*rh+1] - m_new);
                rs += p0 + p1;
                uint2 pu = { f2tf32(p0), f2tf32(p1) };
                *(uint2*)&Ps[row*QS_ST + nj*8 + 2*tg] = pu;
                oacc[nj][2*rh]   *= corr;
                oacc[nj][2*rh+1] *= corr;
            }
            rs += __shfl_xor_sync(0xffffffffu, rs, 1);
            rs += __shfl_xor_sync(0xffffffffu, rs, 2);
            l_i[rh] = l_i[rh]*corr + rs;
            m_i[rh] = m_new;
        }
        __syncwarp();

#pragma unroll
        for (int kk = 0; kk < 64; kk += 8) {
            uint32_t af[4];
            af[0] = __float_as_uint(Ps[r0*QS_ST + kk + tg]);
            af[1] = __float_as_uint(Ps[r1*QS_ST + kk + tg]);
            af[2] = __float_as_uint(Ps[r0*QS_ST + kk + tg + 4]);
            af[3] = __float_as_uint(Ps[r1*QS_ST + kk + tg + 4]);
#pragma unroll
            for (int nj = 0; nj < 8; nj++) {
                uint32_t bf[2];
                bf[0] = __float_as_uint(Vs[(kk + tg)*VS_ST + nj*8 + gid]);
                bf[1] = __float_as_uint(Vs[(kk + tg + 4)*VS_ST + nj*8 + gid]);
                MMA_TF32(oacc[nj], af, bf);
            }
        }
    }

    float inv0 = 1.f / l_i[0], inv1 = 1.f / l_i[1];
#pragma unroll
    for (int nj = 0; nj < 8; nj++) {
        int c = colbase + nj*8 + 2*tg;
        float2 o0 = { oacc[nj][0]*inv0, oacc[nj][1]*inv0 };
        float2 o1 = { oacc[nj][2]*inv1, oacc[nj][3]*inv1 };
        *(float2*)&ctx[(rowbase + q0 + r0)*D_MODEL + c] = o0;
        *(float2*)&ctx[(rowbase + q0 + r1)*D_MODEL + c] = o1;
    }
}

// ---------------- LayerNorm ---------------------------------------------------
__global__ __launch_bounds__(256)
void layernorm_kernel(const float* __restrict__ x, const float* __restrict__ g,
                      const float* __restrict__ bvec, float* __restrict__ out)
{
    int row = blockIdx.x;
    int tid = threadIdx.x;
    const float* xr = x + (size_t)row * D_MODEL;
    float4 v = *(const float4*)&xr[tid*4];
    float s  = v.x + v.y + v.z + v.w;
    float s2 = v.x*v.x + v.y*v.y + v.z*v.z + v.w*v.w;
#pragma unroll
    for (int off = 16; off; off >>= 1) {
        s  += __shfl_xor_sync(0xffffffffu, s,  off);
        s2 += __shfl_xor_sync(0xffffffffu, s2, off);
    }
    __shared__ float ws[8], ws2[8];
    __shared__ float smu, sinv;
    int warp = tid >> 5;
    if ((tid & 31) == 0) { ws[warp] = s; ws2[warp] = s2; }
    __syncthreads();
    if (tid == 0) {
        float a = 0.f, b2 = 0.f;
#pragma unroll
        for (int w = 0; w < 8; w++) { a += ws[w]; b2 += ws2[w]; }
        float mu  = a * (1.f/1024.f);
        float var = b2 * (1.f/1024.f) - mu*mu;
        smu = mu;
        sinv = rsqrtf(var + 1e-5f);
    }
    __syncthreads();
    float mu = smu, inv = sinv;
    float4 gg  = *(const float4*)&g[tid*4];
    float4 bb4 = *(const float4*)&bvec[tid*4];
    float4 o;
    o.x = (v.x - mu)*inv*gg.x + bb4.x;
    o.y = (v.y - mu)*inv*gg.y + bb4.y;
    o.z = (v.z - mu)*inv*gg.z + bb4.z;
    o.w = (v.w - mu)*inv*gg.w + bb4.w;
    *(float4*)&out[(size_t)row * D_MODEL + tid*4] = o;
}

// ---------------- launch ------------------------------------------------------
extern "C" void kernel_launch(void* const* d_in, const int* in_sizes, int n_in,
                              void* d_out, int out_size)
{
    const float* tgt  = (const float*)d_in[0];
    const float* Wq   = (const float*)d_in[1];
    const float* bq   = (const float*)d_in[2];
    const float* Wk   = (const float*)d_in[3];
    const float* bk   = (const float*)d_in[4];
    const float* Wv   = (const float*)d_in[5];
    const float* bv   = (const float*)d_in[6];
    const float* Wo   = (const float*)d_in[7];
    const float* bo   = (const float*)d_in[8];
    const float* W1   = (const float*)d_in[9];
    const float* b1   = (const float*)d_in[10];
    const float* W2   = (const float*)d_in[11];
    const float* b2   = (const float*)d_in[12];
    const float* ln1g = (const float*)d_in[13];
    const float* ln1b = (const float*)d_in[14];
    const float* ln2g = (const float*)d_in[15];
    const float* ln2b = (const float*)d_in[16];
    const float* ropeA = (const float*)d_in[17];
    const float* ropeB = (const float*)d_in[18];
    float* out = (float*)d_out;

    float *pqkv, *pctx, *px, *px1, *pff, *psin, *pcos, *pw, *pbqkv;
    cudaGetSymbolAddress((void**)&pqkv, g_qkv);
    cudaGetSymbolAddress((void**)&pctx, g_ctx);
    cudaGetSymbolAddress((void**)&px,   g_x);
    cudaGetSymbolAddress((void**)&px1,  g_x1);
    cudaGetSymbolAddress((void**)&pff,  g_ff);
    cudaGetSymbolAddress((void**)&psin, g_sinf);
    cudaGetSymbolAddress((void**)&pcos, g_cosf);
    cudaGetSymbolAddress((void**)&pw,   g_w);
    cudaGetSymbolAddress((void**)&pbqkv, g_bqkv);

    float* tWqkv = pw;                 // 1024 x 3072 = 3M
    float* tWo   = pw + 3*1048576;     // 1M
    float* tW1   = pw + 4*1048576;     // 4M
    float* tW2   = pw + 8*1048576;     // 4M

    cudaFuncSetAttribute(attn_mma_kernel,
                         cudaFuncAttributeMaxDynamicSharedMemorySize, ATTN_SMEM);

    // 0. weight preconvert / pack
    cvtw_place_kernel<<<1048576/4/256, 256>>>(Wq, tWqkv, 1048576/4, 0);
    cvtw_place_kernel<<<1048576/4/256, 256>>>(Wk, tWqkv, 1048576/4, 1024);
    cvtw_place_kernel<<<1048576/4/256, 256>>>(Wv, tWqkv, 1048576/4, 2048);
    cvtw_kernel<<<1048576/4/256, 256>>>(Wo, tWo, 1048576/4);
    cvtw_kernel<<<4194304/4/256, 256>>>(W1, tW1, 4194304/4);
    cvtw_kernel<<<4194304/4/256, 256>>>(W2, tW2, 4194304/4);
    pack_bias_kernel<<<QKV_N/256, 256>>>(bq, bk, bv, pbqkv);

    // 1. RoPE factors
    rope_factors_kernel<<<TT, 256>>>(ropeA, ropeB, psin, pcos);

    // 2. fused QKV projection
    dim3 gqkv(QKV_N/128, MROWS/128);
    mma_gemm<<<gqkv, 128, GEMM_SMEM>>>(tgt, tWqkv, pbqkv, nullptr, pqkv,
                                       MROWS, QKV_N, D_MODEL, 0);

    // 3. RoPE on q, k (inside packed qkv)
    rope_apply_kernel<<<(MROWS*512)/256, 256>>>(pqkv, psin, pcos);

    // 4. Attention (tensor core)
    dim3 ga(TT/64, BB*N_HEADS);
    attn_mma_kernel<<<ga, 128, ATTN_SMEM>>>(pqkv, pqkv + 1024, pqkv + 2048,
                                            QKV_N, pctx);

    // 5. Output projection + residual
    dim3 g1024(D_MODEL/128, MROWS/128);
    mma_gemm<<<g1024, 128, GEMM_SMEM>>>(pctx, tWo, bo, tgt, px, MROWS, D_MODEL, D_MODEL, 0);

    // 6. LN1
    layernorm_kernel<<<MROWS, 256>>>(px, ln1g, ln1b, px1);

    // 7. FFN
    dim3 gff1(D_FF/128, MROWS/128);
    mma_gemm<<<gff1, 128, GEMM_SMEM>>>(px1, tW1, b1, nullptr, pff, MROWS, D_FF, D_MODEL, 1);
    mma_gemm<<<g1024, 128, GEMM_SMEM>>>(pff, tW2, b2, px1, px, MROWS, D_MODEL, D_FF, 0);

    // 8. LN2 -> output
    layernorm_kernel<<<MROWS, 256>>>(px, ln2g, ln2b, out);
}